// round 1
// baseline (speedup 1.0000x reference)
#include <cuda_runtime.h>

// Problem constants
#define BB 2
#define CIN 3
#define HH 32
#define WW 32
#define CM 32      // mid channels
#define HQ 16      // mid spatial
#define CO 64      // out channels
#define HP 8       // out spatial
#define NP 64      // HP*HP
#define NI 1024    // HH*WW
#define NE 512     // num embeddings

// Scratch in device globals (no allocations allowed)
__device__ float g_xw1[BB][HQ][HQ][CM][16];  // per-tap conv1 partial sums (pre-bias)
__device__ float g_y1[BB][CM][HQ][HQ];       // relu(conv1)
__device__ float g_y[BB][CO][NP];            // relu(conv2)
__device__ float g_rm[BB][CO][NP];           // 2*(y - q(y)) * mask2
__device__ float g_s[BB][NP][CM][16];        // sum_o rm * w2
__device__ float g_v[BB][NP][16][16];        // sum_m s*mask1*w1sum
__device__ int   g_sel[BB][NI];
__device__ float g_ymask[BB][NP][CO];

// ---------------------------------------------------------------------------
// Kernel A: conv1 per-tap partials + relu(conv1)
// grid = BB*HQ*HQ blocks, 32 threads (one per mid channel m)
__global__ void kA(const float* __restrict__ x, const float* __restrict__ w1,
                   const float* __restrict__ b1) {
    int blk = blockIdx.x;
    int b = blk / (HQ * HQ);
    int q = blk % (HQ * HQ);
    int qh = q / HQ, qw = q % HQ;
    __shared__ float sx[CIN][4][4];
    int t = threadIdx.x;
    for (int idx = t; idx < CIN * 16; idx += 32) {
        int c = idx / 16, k = idx % 16;
        int kh = k / 4, kw = k % 4;
        int xh = 2 * qh - 1 + kh, xw = 2 * qw - 1 + kw;
        float vv = 0.f;
        if (xh >= 0 && xh < HH && xw >= 0 && xw < WW)
            vv = x[((b * CIN + c) * HH + xh) * WW + xw];
        sx[c][kh][kw] = vv;
    }
    __syncthreads();
    int m = t;
    float acc = b1[m];
#pragma unroll
    for (int k = 0; k < 16; k++) {
        int kh = k / 4, kw = k % 4;
        float vv = 0.f;
#pragma unroll
        for (int c = 0; c < CIN; c++)
            vv += w1[(m * CIN + c) * 16 + k] * sx[c][kh][kw];
        g_xw1[b][qh][qw][m][k] = vv;
        acc += vv;
    }
    g_y1[b][m][qh][qw] = fmaxf(acc, 0.f);
}

// ---------------------------------------------------------------------------
// Kernel B: conv2 + relu
// grid = BB*NP blocks, 64 threads (one per out channel o)
__global__ void kB(const float* __restrict__ w2, const float* __restrict__ b2) {
    int blk = blockIdx.x;
    int b = blk / NP, p = blk % NP;
    int ph = p / HP, pw = p % HP;
    __shared__ float sy1[CM][16];
    int t = threadIdx.x;
    for (int idx = t; idx < CM * 16; idx += 64) {
        int m = idx / 16, k = idx % 16;
        int kh = k / 4, kw = k % 4;
        int qh = 2 * ph - 1 + kh, qw = 2 * pw - 1 + kw;
        float vv = 0.f;
        if (qh >= 0 && qh < HQ && qw >= 0 && qw < HQ) vv = g_y1[b][m][qh][qw];
        sy1[m][k] = vv;
    }
    __syncthreads();
    int o = t;
    float acc = b2[o];
    for (int m = 0; m < CM; m++) {
#pragma unroll
        for (int k = 0; k < 16; k++)
            acc += w2[(o * CM + m) * 16 + k] * sy1[m][k];
    }
    g_y[b][o][p] = fmaxf(acc, 0.f);
}

// ---------------------------------------------------------------------------
// Kernel C: hopfield(q) on y, produce rm = 2*(y - q(y)) * (y>0)
// grid = BB*NP blocks, 128 threads
__global__ void kC(const float* __restrict__ Km, const float* __restrict__ Vm) {
    int blk = blockIdx.x;
    int b = blk / NP, p = blk % NP;
    __shared__ float yv[CO];
    __shared__ float wexp[NE];
    __shared__ float red[128];
    int t = threadIdx.x;
    if (t < CO) yv[t] = g_y[b][t][p];
    __syncthreads();
    float l[4];
    float lmax = -1e30f;
#pragma unroll
    for (int j = 0; j < 4; j++) {
        int k = t * 4 + j;
        float acc = 0.f;
#pragma unroll 8
        for (int o = 0; o < CO; o++) acc += Km[k * CO + o] * yv[o];
        l[j] = 0.125f * acc;
        lmax = fmaxf(lmax, l[j]);
    }
    red[t] = lmax;
    __syncthreads();
    for (int s = 64; s > 0; s >>= 1) {
        if (t < s) red[t] = fmaxf(red[t], red[t + s]);
        __syncthreads();
    }
    lmax = red[0];
    __syncthreads();
    float ssum = 0.f;
#pragma unroll
    for (int j = 0; j < 4; j++) {
        float e = expf(l[j] - lmax);
        wexp[t * 4 + j] = e;
        ssum += e;
    }
    red[t] = ssum;
    __syncthreads();
    for (int s = 64; s > 0; s >>= 1) {
        if (t < s) red[t] += red[t + s];
        __syncthreads();
    }
    float inv = 1.f / red[0];
    if (t < CO) {
        int o = t;
        float acc = 0.f;
        for (int k = 0; k < NE; k++) acc += wexp[k] * Vm[k * CO + o];
        float e = acc * inv;
        float yy = yv[o];
        g_rm[b][o][p] = (yy > 0.f) ? 2.f * (yy - e) : 0.f;
    }
}

// ---------------------------------------------------------------------------
// Kernel D: s[b,p,m,k2] = sum_o rm[b,o,p] * w2[o,m,k2]
// grid = BB*NP blocks, 512 threads (m*16+k2)
__global__ void kD(const float* __restrict__ w2) {
    int blk = blockIdx.x;
    int b = blk / NP, p = blk % NP;
    __shared__ float r[CO];
    int t = threadIdx.x;
    if (t < CO) r[t] = g_rm[b][t][p];
    __syncthreads();
    int m = t / 16, k2 = t % 16;
    float acc = 0.f;
#pragma unroll 8
    for (int o = 0; o < CO; o++) acc += r[o] * w2[(o * CM + m) * 16 + k2];
    g_s[b][p][m][k2] = acc;
}

// ---------------------------------------------------------------------------
// Kernel E: v[b,p,k2,k1] = sum_m s[b,p,m,k2]*mask1[b,m,q(p,k2)]*w1sum[m,k1]
// grid = BB*NP blocks, 256 threads (k2*16+k1)
__global__ void kE(const float* __restrict__ w1) {
    int blk = blockIdx.x;
    int b = blk / NP, p = blk % NP;
    int ph = p / HP, pw = p % HP;
    int t = threadIdx.x;
    __shared__ float w1s[CM][16];
    __shared__ float sm[CM][16];
    for (int idx = t; idx < CM * 16; idx += 256) {
        int m = idx / 16, k = idx % 16;
        float acc = 0.f;
#pragma unroll
        for (int c = 0; c < CIN; c++) acc += w1[(m * CIN + c) * 16 + k];
        w1s[m][k] = acc;
        int kh = k / 4, kw = k % 4;
        int qh = 2 * ph - 1 + kh, qw = 2 * pw - 1 + kw;
        float sv = 0.f;
        if (qh >= 0 && qh < HQ && qw >= 0 && qw < HQ && g_y1[b][m][qh][qw] > 0.f)
            sv = g_s[b][p][m][k];
        sm[m][k] = sv;
    }
    __syncthreads();
    int k2 = t / 16, k1 = t % 16;
    float acc = 0.f;
#pragma unroll 8
    for (int m = 0; m < CM; m++) acc += sm[m][k2] * w1s[m][k1];
    g_v[b][p][k2][k1] = acc;
}

// ---------------------------------------------------------------------------
// Kernel F: sel[b,i] = argmin_p e_total[b,p,i] (first occurrence), plus zero y_masked
// grid = 8 blocks, 256 threads (one thread per (b,i))
__global__ void kF() {
    int gid = blockIdx.x * 256 + threadIdx.x;  // 0..2047
    int b = gid / NI, i = gid % NI;
    int ih = i / WW, iw = i % WW;
    int qh0 = (ih + 1) >> 1, qw0 = (iw + 1) >> 1;
    float best = 1e30f;
    int bestp = 0;
    for (int p = 0; p < NP; p++) {
        int ph = p >> 3, pw = p & 7;
        float e = 0.f;
#pragma unroll
        for (int dqh = 0; dqh < 2; dqh++) {
            int qh = qh0 - dqh;
            if (qh < 0 || qh >= HQ) continue;
            int k2h = qh - 2 * ph + 1;
            if (k2h < 0 || k2h > 3) continue;
            int k1h = ih + 1 - 2 * qh;  // always in [0,3]
#pragma unroll
            for (int dqw = 0; dqw < 2; dqw++) {
                int qw = qw0 - dqw;
                if (qw < 0 || qw >= HQ) continue;
                int k2w = qw - 2 * pw + 1;
                if (k2w < 0 || k2w > 3) continue;
                int k1w = iw + 1 - 2 * qw;
                e += g_v[b][p][k2h * 4 + k2w][k1h * 4 + k1w];
            }
        }
        if (e < best) { best = e; bestp = p; }
    }
    g_sel[b][i] = bestp;
    // zero y_masked for next kernel
    float* ym = &g_ymask[0][0][0];
    for (int z = gid; z < BB * NP * CO; z += 2048) ym[z] = 0.f;
}

// ---------------------------------------------------------------------------
// Kernel G: contrib[b,i,o] scattered into y_masked[b,sel,o]
// grid = BB*NI blocks, 64 threads (one per o)
__global__ void kG(const float* __restrict__ w2) {
    int blk = blockIdx.x;
    int b = blk / NI, i = blk % NI;
    int ih = i / WW, iw = i % WW;
    int p = g_sel[b][i];
    int ph = p >> 3, pw = p & 7;
    __shared__ float am[4][CM];
    __shared__ int k2idx[4];
    __shared__ int validq[4];
    int t = threadIdx.x;
    int qh0 = (ih + 1) >> 1, qw0 = (iw + 1) >> 1;
    if (t < 4) {
        int dqh = t >> 1, dqw = t & 1;
        int qh = qh0 - dqh, qw = qw0 - dqw;
        int ok = (qh >= 0 && qh < HQ && qw >= 0 && qw < HQ);
        int k2h = qh - 2 * ph + 1, k2w = qw - 2 * pw + 1;
        ok = ok && (k2h >= 0) && (k2h <= 3) && (k2w >= 0) && (k2w <= 3);
        validq[t] = ok;
        k2idx[t] = ok ? (k2h * 4 + k2w) : 0;
    }
    __syncthreads();
    for (int idx = t; idx < 4 * CM; idx += 64) {
        int qc = idx >> 5, m = idx & 31;
        int dqh = qc >> 1, dqw = qc & 1;
        int qh = qh0 - dqh, qw = qw0 - dqw;
        float vv = 0.f;
        if (validq[qc] && g_y1[b][m][qh][qw] > 0.f) {
            int k1 = (ih + 1 - 2 * qh) * 4 + (iw + 1 - 2 * qw);
            vv = g_xw1[b][qh][qw][m][k1];
        }
        am[qc][m] = vv;
    }
    __syncthreads();
    int o = t;
    float yy = g_y[b][o][p];
    if (yy > 0.f) {
        float acc = 0.f;
#pragma unroll
        for (int qc = 0; qc < 4; qc++) {
            int k2 = k2idx[qc];
            const float* w2p = &w2[(o * CM) * 16 + k2];
#pragma unroll 8
            for (int m = 0; m < CM; m++) acc += w2p[m * 16] * am[qc][m];
        }
        if (acc != 0.f) atomicAdd(&g_ymask[b][p][o], acc);
    }
}

// ---------------------------------------------------------------------------
// Kernel H: final hopfield on y_masked -> output (B, CO, HP, HP)
// grid = BB*NP blocks, 128 threads
__global__ void kH(const float* __restrict__ Km, const float* __restrict__ Vm,
                   float* __restrict__ out) {
    int blk = blockIdx.x;
    int b = blk / NP, p = blk % NP;
    __shared__ float yv[CO];
    __shared__ float wexp[NE];
    __shared__ float red[128];
    int t = threadIdx.x;
    if (t < CO) yv[t] = g_ymask[b][p][t];
    __syncthreads();
    float l[4];
    float lmax = -1e30f;
#pragma unroll
    for (int j = 0; j < 4; j++) {
        int k = t * 4 + j;
        float acc = 0.f;
#pragma unroll 8
        for (int o = 0; o < CO; o++) acc += Km[k * CO + o] * yv[o];
        l[j] = 0.125f * acc;
        lmax = fmaxf(lmax, l[j]);
    }
    red[t] = lmax;
    __syncthreads();
    for (int s = 64; s > 0; s >>= 1) {
        if (t < s) red[t] = fmaxf(red[t], red[t + s]);
        __syncthreads();
    }
    lmax = red[0];
    __syncthreads();
    float ssum = 0.f;
#pragma unroll
    for (int j = 0; j < 4; j++) {
        float e = expf(l[j] - lmax);
        wexp[t * 4 + j] = e;
        ssum += e;
    }
    red[t] = ssum;
    __syncthreads();
    for (int s = 64; s > 0; s >>= 1) {
        if (t < s) red[t] += red[t + s];
        __syncthreads();
    }
    float inv = 1.f / red[0];
    if (t < CO) {
        int o = t;
        float acc = 0.f;
        for (int k = 0; k < NE; k++) acc += wexp[k] * Vm[k * CO + o];
        out[(b * CO + o) * NP + p] = acc * inv;
    }
}

// ---------------------------------------------------------------------------
extern "C" void kernel_launch(void* const* d_in, const int* in_sizes, int n_in,
                              void* d_out, int out_size) {
    const float* x  = (const float*)d_in[0];  // (2,3,32,32)
    const float* w1 = (const float*)d_in[1];  // (32,3,4,4)
    const float* b1 = (const float*)d_in[2];  // (32,)
    const float* w2 = (const float*)d_in[3];  // (64,32,4,4)
    const float* b2 = (const float*)d_in[4];  // (64,)
    const float* Km = (const float*)d_in[5];  // (512,64)
    const float* Vm = (const float*)d_in[6];  // (512,64)
    float* out = (float*)d_out;               // (2,64,8,8)

    kA<<<BB * HQ * HQ, 32>>>(x, w1, b1);
    kB<<<BB * NP, 64>>>(w2, b2);
    kC<<<BB * NP, 128>>>(Km, Vm);
    kD<<<BB * NP, 512>>>(w2);
    kE<<<BB * NP, 256>>>(w1);
    kF<<<8, 256>>>();
    kG<<<BB * NI, 64>>>(w2);
    kH<<<BB * NP, 128>>>(Km, Vm, out);
}

// round 2
// speedup vs baseline: 1.3053x; 1.3053x over previous
#include <cuda_runtime.h>

// Problem constants
#define BB 2
#define CIN 3
#define HH 32
#define WW 32
#define CM 32      // mid channels
#define HQ 16      // mid spatial
#define CO 64      // out channels
#define HP 8       // out spatial
#define NP 64      // HP*HP
#define NI 1024    // HH*WW
#define NE 512     // num embeddings

// Scratch in device globals (no allocations allowed)
__device__ float g_xw1[BB][HQ][HQ][CM][16];  // per-tap conv1 partial sums (pre-bias)
__device__ float g_y1[BB][CM][HQ][HQ];       // relu(conv1)
__device__ float g_y[BB][CO][NP];            // relu(conv2)
__device__ float g_rm[BB][CO][NP];           // 2*(y - q(y)) * mask2
__device__ float g_v[BB][NP][16][16];        // sum_m s*mask1*w1sum
__device__ float g_ymask[BB][NP][CO];

// ---------------------------------------------------------------------------
// Kernel A: conv1 per-tap partials + relu(conv1); also zero g_ymask
// grid = BB*HQ*HQ = 512 blocks, 32 threads (one per mid channel m)
__global__ void kA(const float* __restrict__ x, const float* __restrict__ w1,
                   const float* __restrict__ b1) {
    int blk = blockIdx.x;
    int b = blk / (HQ * HQ);
    int q = blk % (HQ * HQ);
    int qh = q / HQ, qw = q % HQ;
    __shared__ float sx[CIN][4][4];
    int t = threadIdx.x;
    // zero ymask (8192 floats across 16384 threads)
    int gid = blk * 32 + t;
    if (gid < BB * NP * CO) (&g_ymask[0][0][0])[gid] = 0.f;
    for (int idx = t; idx < CIN * 16; idx += 32) {
        int c = idx / 16, k = idx % 16;
        int kh = k / 4, kw = k % 4;
        int xh = 2 * qh - 1 + kh, xw = 2 * qw - 1 + kw;
        float vv = 0.f;
        if (xh >= 0 && xh < HH && xw >= 0 && xw < WW)
            vv = x[((b * CIN + c) * HH + xh) * WW + xw];
        sx[c][kh][kw] = vv;
    }
    __syncthreads();
    int m = t;
    float acc = b1[m];
#pragma unroll
    for (int k = 0; k < 16; k++) {
        int kh = k / 4, kw = k % 4;
        float vv = 0.f;
#pragma unroll
        for (int c = 0; c < CIN; c++)
            vv += w1[(m * CIN + c) * 16 + k] * sx[c][kh][kw];
        g_xw1[b][qh][qw][m][k] = vv;
        acc += vv;
    }
    g_y1[b][m][qh][qw] = fmaxf(acc, 0.f);
}

// ---------------------------------------------------------------------------
// Kernel BC: conv2 + relu + hopfield -> rm residual, fused per (b,p)
// grid = BB*NP = 128 blocks, 256 threads
__global__ void kBC(const float* __restrict__ w2, const float* __restrict__ b2,
                    const float* __restrict__ Km, const float* __restrict__ Vm) {
    int blk = blockIdx.x;
    int b = blk / NP, p = blk % NP;
    int ph = p / HP, pw = p % HP;
    __shared__ float sy1[CM][16];
    __shared__ float yv[CO];
    __shared__ float wexp[NE];
    __shared__ float red[256];
    __shared__ float red2[4][CO];
    int t = threadIdx.x;
    for (int idx = t; idx < CM * 16; idx += 256) {
        int m = idx / 16, k = idx % 16;
        int kh = k / 4, kw = k % 4;
        int qh = 2 * ph - 1 + kh, qw = 2 * pw - 1 + kw;
        float vv = 0.f;
        if (qh >= 0 && qh < HQ && qw >= 0 && qw < HQ) vv = g_y1[b][m][qh][qw];
        sy1[m][k] = vv;
    }
    __syncthreads();
    // conv2: split m over 4 groups of 8
    {
        int o = t & 63, q4 = t >> 6;
        float acc = 0.f;
#pragma unroll
        for (int mm = 0; mm < 8; mm++) {
            int m = q4 * 8 + mm;
#pragma unroll
            for (int k = 0; k < 16; k++)
                acc += w2[(o * CM + m) * 16 + k] * sy1[m][k];
        }
        red2[q4][o] = acc;
    }
    __syncthreads();
    if (t < CO) {
        float acc = b2[t] + red2[0][t] + red2[1][t] + red2[2][t] + red2[3][t];
        float yy = fmaxf(acc, 0.f);
        yv[t] = yy;
        g_y[b][t][p] = yy;
    }
    __syncthreads();
    // logits: 2 keys per thread
    float l[2];
    float lmax = -1e30f;
#pragma unroll
    for (int j = 0; j < 2; j++) {
        int k = t * 2 + j;
        float acc = 0.f;
#pragma unroll 8
        for (int o = 0; o < CO; o++) acc += Km[k * CO + o] * yv[o];
        l[j] = 0.125f * acc;
        lmax = fmaxf(lmax, l[j]);
    }
    red[t] = lmax;
    __syncthreads();
    for (int s = 128; s > 0; s >>= 1) {
        if (t < s) red[t] = fmaxf(red[t], red[t + s]);
        __syncthreads();
    }
    lmax = red[0];
    __syncthreads();
    float ssum = 0.f;
#pragma unroll
    for (int j = 0; j < 2; j++) {
        float e = expf(l[j] - lmax);
        wexp[t * 2 + j] = e;
        ssum += e;
    }
    red[t] = ssum;
    __syncthreads();
    for (int s = 128; s > 0; s >>= 1) {
        if (t < s) red[t] += red[t + s];
        __syncthreads();
    }
    float inv = 1.f / red[0];
    __syncthreads();
    // V accumulation: split k over 4 groups of 128
    {
        int o = t & 63, q4 = t >> 6;
        float acc = 0.f;
        int k0 = q4 * 128;
#pragma unroll 8
        for (int kk = 0; kk < 128; kk++) acc += wexp[k0 + kk] * Vm[(k0 + kk) * CO + o];
        red2[q4][o] = acc;
    }
    __syncthreads();
    if (t < CO) {
        float e = (red2[0][t] + red2[1][t] + red2[2][t] + red2[3][t]) * inv;
        float yy = yv[t];
        g_rm[b][t][p] = (yy > 0.f) ? 2.f * (yy - e) : 0.f;
    }
}

// ---------------------------------------------------------------------------
// Kernel DE: s (smem only) then v, fused per (b,p)
// grid = BB*NP = 128 blocks, 512 threads
__global__ void kDE(const float* __restrict__ w1, const float* __restrict__ w2) {
    int blk = blockIdx.x;
    int b = blk / NP, p = blk % NP;
    int ph = p / HP, pw = p % HP;
    __shared__ float r[CO];
    __shared__ float w1s[CM][16];
    __shared__ float sm[CM][16];
    int t = threadIdx.x;
    if (t < CO) r[t] = g_rm[b][t][p];
    {
        int m = t / 16, k = t % 16;
        float acc = 0.f;
#pragma unroll
        for (int c = 0; c < CIN; c++) acc += w1[(m * CIN + c) * 16 + k];
        w1s[m][k] = acc;
    }
    __syncthreads();
    {
        int m = t / 16, k2 = t % 16;
        float acc = 0.f;
#pragma unroll 8
        for (int o = 0; o < CO; o++) acc += r[o] * w2[(o * CM + m) * 16 + k2];
        // apply mask1 at q(p,k2)
        int kh = k2 / 4, kw = k2 % 4;
        int qh = 2 * ph - 1 + kh, qw = 2 * pw - 1 + kw;
        float sv = 0.f;
        if (qh >= 0 && qh < HQ && qw >= 0 && qw < HQ && g_y1[b][m][qh][qw] > 0.f)
            sv = acc;
        sm[m][k2] = sv;
    }
    __syncthreads();
    if (t < 256) {
        int k2 = t / 16, k1 = t % 16;
        float acc = 0.f;
#pragma unroll 8
        for (int m = 0; m < CM; m++) acc += sm[m][k2] * w1s[m][k1];
        g_v[b][p][k2][k1] = acc;
    }
}

// ---------------------------------------------------------------------------
// Kernel FG: per-(b,i) argmin over p (first-occurrence) + scatter contrib
// grid = BB*NI = 2048 blocks, 64 threads
__global__ void kFG(const float* __restrict__ w2) {
    int blk = blockIdx.x;
    int b = blk / NI, i = blk % NI;
    int ih = i / WW, iw = i % WW;
    int qh0 = (ih + 1) >> 1, qw0 = (iw + 1) >> 1;
    __shared__ float re[64];
    __shared__ int rp[64];
    __shared__ float am[4][CM];
    __shared__ int k2idx[4];
    __shared__ int validq[4];
    int t = threadIdx.x;
    // --- argmin: one p per thread
    {
        int p = t;
        int ph = p >> 3, pw = p & 7;
        float e = 0.f;
#pragma unroll
        for (int dqh = 0; dqh < 2; dqh++) {
            int qh = qh0 - dqh;
            int k2h = qh - 2 * ph + 1;
            if (qh < 0 || qh >= HQ || k2h < 0 || k2h > 3) continue;
            int k1h = ih + 1 - 2 * qh;
#pragma unroll
            for (int dqw = 0; dqw < 2; dqw++) {
                int qw = qw0 - dqw;
                int k2w = qw - 2 * pw + 1;
                if (qw < 0 || qw >= HQ || k2w < 0 || k2w > 3) continue;
                int k1w = iw + 1 - 2 * qw;
                e += g_v[b][p][k2h * 4 + k2w][k1h * 4 + k1w];
            }
        }
        re[t] = e;
        rp[t] = p;
    }
    __syncthreads();
    for (int s = 32; s > 0; s >>= 1) {
        if (t < s) {
            float ea = re[t], eb = re[t + s];
            int pa = rp[t], pb = rp[t + s];
            // first occurrence: lexicographic (e, p)
            if (eb < ea || (eb == ea && pb < pa)) { re[t] = eb; rp[t] = pb; }
        }
        __syncthreads();
    }
    int p = rp[0];
    int ph = p >> 3, pw = p & 7;
    // --- scatter contrib into ymask[b][p][:]
    if (t < 4) {
        int dqh = t >> 1, dqw = t & 1;
        int qh = qh0 - dqh, qw = qw0 - dqw;
        int ok = (qh >= 0 && qh < HQ && qw >= 0 && qw < HQ);
        int k2h = qh - 2 * ph + 1, k2w = qw - 2 * pw + 1;
        ok = ok && (k2h >= 0) && (k2h <= 3) && (k2w >= 0) && (k2w <= 3);
        validq[t] = ok;
        k2idx[t] = ok ? (k2h * 4 + k2w) : 0;
    }
    __syncthreads();
    for (int idx = t; idx < 4 * CM; idx += 64) {
        int qc = idx >> 5, m = idx & 31;
        int dqh = qc >> 1, dqw = qc & 1;
        int qh = qh0 - dqh, qw = qw0 - dqw;
        float vv = 0.f;
        if (validq[qc] && g_y1[b][m][qh][qw] > 0.f) {
            int k1 = (ih + 1 - 2 * qh) * 4 + (iw + 1 - 2 * qw);
            vv = g_xw1[b][qh][qw][m][k1];
        }
        am[qc][m] = vv;
    }
    __syncthreads();
    int o = t;
    float yy = g_y[b][o][p];
    if (yy > 0.f) {
        float acc = 0.f;
#pragma unroll
        for (int qc = 0; qc < 4; qc++) {
            int k2 = k2idx[qc];
            const float* w2p = &w2[(o * CM) * 16 + k2];
#pragma unroll 8
            for (int m = 0; m < CM; m++) acc += w2p[m * 16] * am[qc][m];
        }
        if (acc != 0.f) atomicAdd(&g_ymask[b][p][o], acc);
    }
}

// ---------------------------------------------------------------------------
// Kernel H: final hopfield on y_masked -> output (B, CO, HP, HP)
// grid = BB*NP = 128 blocks, 256 threads
__global__ void kH(const float* __restrict__ Km, const float* __restrict__ Vm,
                   float* __restrict__ out) {
    int blk = blockIdx.x;
    int b = blk / NP, p = blk % NP;
    __shared__ float yv[CO];
    __shared__ float wexp[NE];
    __shared__ float red[256];
    __shared__ float red2[4][CO];
    int t = threadIdx.x;
    if (t < CO) yv[t] = g_ymask[b][p][t];
    __syncthreads();
    float l[2];
    float lmax = -1e30f;
#pragma unroll
    for (int j = 0; j < 2; j++) {
        int k = t * 2 + j;
        float acc = 0.f;
#pragma unroll 8
        for (int o = 0; o < CO; o++) acc += Km[k * CO + o] * yv[o];
        l[j] = 0.125f * acc;
        lmax = fmaxf(lmax, l[j]);
    }
    red[t] = lmax;
    __syncthreads();
    for (int s = 128; s > 0; s >>= 1) {
        if (t < s) red[t] = fmaxf(red[t], red[t + s]);
        __syncthreads();
    }
    lmax = red[0];
    __syncthreads();
    float ssum = 0.f;
#pragma unroll
    for (int j = 0; j < 2; j++) {
        float e = expf(l[j] - lmax);
        wexp[t * 2 + j] = e;
        ssum += e;
    }
    red[t] = ssum;
    __syncthreads();
    for (int s = 128; s > 0; s >>= 1) {
        if (t < s) red[t] += red[t + s];
        __syncthreads();
    }
    float inv = 1.f / red[0];
    __syncthreads();
    {
        int o = t & 63, q4 = t >> 6;
        float acc = 0.f;
        int k0 = q4 * 128;
#pragma unroll 8
        for (int kk = 0; kk < 128; kk++) acc += wexp[k0 + kk] * Vm[(k0 + kk) * CO + o];
        red2[q4][o] = acc;
    }
    __syncthreads();
    if (t < CO) {
        float acc = (red2[0][t] + red2[1][t] + red2[2][t] + red2[3][t]) * inv;
        out[(b * CO + t) * NP + p] = acc;
    }
}

// ---------------------------------------------------------------------------
extern "C" void kernel_launch(void* const* d_in, const int* in_sizes, int n_in,
                              void* d_out, int out_size) {
    const float* x  = (const float*)d_in[0];  // (2,3,32,32)
    const float* w1 = (const float*)d_in[1];  // (32,3,4,4)
    const float* b1 = (const float*)d_in[2];  // (32,)
    const float* w2 = (const float*)d_in[3];  // (64,32,4,4)
    const float* b2 = (const float*)d_in[4];  // (64,)
    const float* Km = (const float*)d_in[5];  // (512,64)
    const float* Vm = (const float*)d_in[6];  // (512,64)
    float* out = (float*)d_out;               // (2,64,8,8)

    kA<<<BB * HQ * HQ, 32>>>(x, w1, b1);
    kBC<<<BB * NP, 256>>>(w2, b2, Km, Vm);
    kDE<<<BB * NP, 512>>>(w1, w2);
    kFG<<<BB * NI, 64>>>(w2);
    kH<<<BB * NP, 256>>>(Km, Vm, out);
}

// round 3
// speedup vs baseline: 1.7817x; 1.3650x over previous
#include <cuda_runtime.h>
#include <math_constants.h>

// Problem constants
#define BB 2
#define CIN 3
#define HH 32
#define WW 32
#define CM 32      // mid channels
#define HQ 16      // mid spatial
#define CO 64      // out channels
#define HP 8       // out spatial
#define NP 64      // HP*HP
#define NI 1024    // HH*WW
#define NE 512     // num embeddings

// Scratch in device globals (no allocations allowed)
__device__ float g_xw1[BB][HQ][HQ][16][CM];  // per-tap conv1 partials, [k1][m] (m contiguous)
__device__ float g_y1[BB][HQ][HQ][CM];       // relu(conv1), m contiguous
__device__ float g_y[BB][NP][CO];            // relu(conv2), o contiguous
__device__ float g_rm[BB][NP][CO];           // 2*(y - q(y)) * mask2
__device__ float g_v[BB][NP][16][16];        // [k2][k1]
__device__ float g_ymask[BB][NP][CO];
__device__ float g_w2t[16][CM][CO];          // w2 transposed: [k2][m][o], o contiguous
__device__ float g_KmT[CO][NE];              // K transposed: [o][k], k contiguous

// ---------------------------------------------------------------------------
// Kernel A: conv1 per-tap partials + relu(conv1); zero g_ymask; build w2t, KmT
// grid = BB*HQ*HQ = 512 blocks, 32 threads (one per mid channel m)
__global__ void kA(const float* __restrict__ x, const float* __restrict__ w1,
                   const float* __restrict__ b1, const float* __restrict__ w2,
                   const float* __restrict__ Km) {
    int blk = blockIdx.x;
    int b = blk / (HQ * HQ);
    int q = blk % (HQ * HQ);
    int qh = q / HQ, qw = q % HQ;
    __shared__ float sx[CIN][4][4];
    int t = threadIdx.x;
    int gid = blk * 32 + t;  // 0..16383
    // zero ymask (8192 floats)
    if (gid < BB * NP * CO) (&g_ymask[0][0][0])[gid] = 0.f;
    // build transposes: 32768 entries each, 2 per thread
#pragma unroll
    for (int r = 0; r < 2; r++) {
        int idx = gid + r * 16384;  // 0..32767
        {
            int k2 = idx >> 11, m = (idx >> 6) & 31, o = idx & 63;
            g_w2t[k2][m][o] = w2[(o * CM + m) * 16 + k2];
        }
        {
            int o2 = idx >> 9, k = idx & 511;
            g_KmT[o2][k] = Km[k * CO + o2];
        }
    }
    for (int idx = t; idx < CIN * 16; idx += 32) {
        int c = idx / 16, k = idx % 16;
        int kh = k / 4, kw = k % 4;
        int xh = 2 * qh - 1 + kh, xw = 2 * qw - 1 + kw;
        float vv = 0.f;
        if (xh >= 0 && xh < HH && xw >= 0 && xw < WW)
            vv = x[((b * CIN + c) * HH + xh) * WW + xw];
        sx[c][kh][kw] = vv;
    }
    __syncthreads();
    int m = t;
    float acc = b1[m];
#pragma unroll
    for (int k = 0; k < 16; k++) {
        int kh = k / 4, kw = k % 4;
        float vv = 0.f;
#pragma unroll
        for (int c = 0; c < CIN; c++)
            vv += w1[(m * CIN + c) * 16 + k] * sx[c][kh][kw];
        g_xw1[b][qh][qw][k][m] = vv;   // coalesced over m per k
        acc += vv;
    }
    g_y1[b][qh][qw][m] = fmaxf(acc, 0.f);
}

// ---------------------------------------------------------------------------
// Kernel BC: conv2 + relu + hopfield -> rm residual, fused per (b,p)
// grid = BB*NP = 128 blocks, 256 threads
__global__ void kBC(const float* __restrict__ b2, const float* __restrict__ Vm) {
    int blk = blockIdx.x;
    int b = blk / NP, p = blk % NP;
    int ph = p / HP, pw = p % HP;
    __shared__ float sy1[16][CM];   // [k][m]
    __shared__ float yv[CO];
    __shared__ float wexp[NE];
    __shared__ float red[256];
    __shared__ float red2[4][CO];
    int t = threadIdx.x;
    for (int idx = t; idx < CM * 16; idx += 256) {
        int k = idx >> 5, m = idx & 31;   // m contiguous across threads
        int kh = k / 4, kw = k % 4;
        int qh = 2 * ph - 1 + kh, qw = 2 * pw - 1 + kw;
        float vv = 0.f;
        if (qh >= 0 && qh < HQ && qw >= 0 && qw < HQ) vv = g_y1[b][qh][qw][m];
        sy1[k][m] = vv;
    }
    __syncthreads();
    // conv2 via w2t[k][m][o] (coalesced over o): split m over 4 groups of 8
    {
        int o = t & 63, q4 = t >> 6;
        float acc = 0.f;
#pragma unroll
        for (int mm = 0; mm < 8; mm++) {
            int m = q4 * 8 + mm;
#pragma unroll
            for (int k = 0; k < 16; k++)
                acc += g_w2t[k][m][o] * sy1[k][m];
        }
        red2[q4][o] = acc;
    }
    __syncthreads();
    if (t < CO) {
        float acc = b2[t] + red2[0][t] + red2[1][t] + red2[2][t] + red2[3][t];
        float yy = fmaxf(acc, 0.f);
        yv[t] = yy;
        g_y[b][p][t] = yy;
    }
    __syncthreads();
    // logits via KmT[o][k] (coalesced over k): k = t + 256*j
    float l[2];
    float lmax = -1e30f;
#pragma unroll
    for (int j = 0; j < 2; j++) {
        int k = t + 256 * j;
        float acc = 0.f;
#pragma unroll 8
        for (int o = 0; o < CO; o++) acc += g_KmT[o][k] * yv[o];
        l[j] = 0.125f * acc;
        lmax = fmaxf(lmax, l[j]);
    }
    red[t] = lmax;
    __syncthreads();
    for (int s = 128; s > 0; s >>= 1) {
        if (t < s) red[t] = fmaxf(red[t], red[t + s]);
        __syncthreads();
    }
    lmax = red[0];
    __syncthreads();
    float ssum = 0.f;
#pragma unroll
    for (int j = 0; j < 2; j++) {
        float e = expf(l[j] - lmax);
        wexp[t + 256 * j] = e;
        ssum += e;
    }
    red[t] = ssum;
    __syncthreads();
    for (int s = 128; s > 0; s >>= 1) {
        if (t < s) red[t] += red[t + s];
        __syncthreads();
    }
    float inv = 1.f / red[0];
    __syncthreads();
    // V accumulation: split k over 4 groups of 128 (Vm coalesced over o)
    {
        int o = t & 63, q4 = t >> 6;
        float acc = 0.f;
        int k0 = q4 * 128;
#pragma unroll 8
        for (int kk = 0; kk < 128; kk++) acc += wexp[k0 + kk] * Vm[(k0 + kk) * CO + o];
        red2[q4][o] = acc;
    }
    __syncthreads();
    if (t < CO) {
        float e = (red2[0][t] + red2[1][t] + red2[2][t] + red2[3][t]) * inv;
        float yy = yv[t];
        g_rm[b][p][t] = (yy > 0.f) ? 2.f * (yy - e) : 0.f;
    }
}

// ---------------------------------------------------------------------------
// Kernel DE: s (smem only, w2 via coalesced smem tiles) then v, fused per (b,p)
// grid = BB*NP = 128 blocks, 512 threads
__global__ void kDE(const float* __restrict__ w1, const float* __restrict__ w2) {
    int blk = blockIdx.x;
    int b = blk / NP, p = blk % NP;
    int ph = p / HP, pw = p % HP;
    __shared__ float r[CO];
    __shared__ float w1s[CM][16];
    __shared__ float sm[CM][16];
    __shared__ float sw[16][512];   // 32KB tile of w2 (16 o-rows)
    int t = threadIdx.x;
    if (t < CO) r[t] = g_rm[b][p][t];
    {
        int m = t / 16, k = t % 16;
        float acc = 0.f;
#pragma unroll
        for (int c = 0; c < CIN; c++) acc += w1[(m * CIN + c) * 16 + k];
        w1s[m][k] = acc;
    }
    __syncthreads();
    // s[m][k2] = sum_o r[o]*w2[o*512 + (m*16+k2)] via 4 coalesced tiles
    float acc = 0.f;
    for (int c = 0; c < 4; c++) {
#pragma unroll
        for (int j = 0; j < 16; j++) sw[j][t] = w2[(c * 16 + j) * 512 + t];
        __syncthreads();
#pragma unroll
        for (int j = 0; j < 16; j++) acc += r[c * 16 + j] * sw[j][t];
        __syncthreads();
    }
    {
        int m = t / 16, k2 = t % 16;
        int kh = k2 / 4, kw = k2 % 4;
        int qh = 2 * ph - 1 + kh, qw = 2 * pw - 1 + kw;
        float sv = 0.f;
        if (qh >= 0 && qh < HQ && qw >= 0 && qw < HQ && g_y1[b][qh][qw][m] > 0.f)
            sv = acc;
        sm[m][k2] = sv;
    }
    __syncthreads();
    if (t < 256) {
        int k2 = t / 16, k1 = t % 16;
        float a2 = 0.f;
#pragma unroll 8
        for (int m = 0; m < CM; m++) a2 += sm[m][k2] * w1s[m][k1];
        g_v[b][p][k2][k1] = a2;
    }
}

// ---------------------------------------------------------------------------
// Kernel FG: one block per (b, ih) row: argmin over p for 32 iw + scatter contrib
// grid = BB*HH = 64 blocks, 256 threads
__global__ void kFG() {
    int blk = blockIdx.x;
    int b = blk / HH, ih = blk % HH;
    int qh0 = (ih + 1) >> 1;
    __shared__ float sv[2][64][16];    // staged v sub-blocks, 8KB
    __shared__ int sel_s[32];
    __shared__ float am_s[4][4][32];   // [iw-group][qc][m]
    int t = threadIdx.x;
    // stage sv: sv[qc][p][k2w*4+k1w] = v[b][p][k2h*4+k2w][k1h*4+k1w] (0 if invalid)
    for (int idx = t; idx < 2 * 64 * 4; idx += 256) {
        int qc = idx >> 8;
        int rem = idx & 255;
        int p = rem >> 2, k2w = rem & 3;
        int qh = qh0 - qc;
        int ph = p >> 3;
        int k2h = qh - 2 * ph + 1;
        int k1h = ih + 1 - 2 * qh;
        float4 val = make_float4(0.f, 0.f, 0.f, 0.f);
        if (qh >= 0 && qh < HQ && k2h >= 0 && k2h <= 3)
            val = *(const float4*)&g_v[b][p][k2h * 4 + k2w][k1h * 4];
        *(float4*)&sv[qc][p][k2w * 4] = val;
    }
    __syncthreads();
    // argmin: thread t = iw*8 + g; thread scans p = g*8..g*8+7 ascending
    {
        int iw = t >> 3, g = t & 7;
        int qw0 = (iw + 1) >> 1;
        float best = CUDART_INF_F;
        int bestp = 127;
        for (int pp = 0; pp < 8; pp++) {
            int p = g * 8 + pp;
            int ph = p >> 3, pw = p & 7;
            float e = 0.f;
#pragma unroll
            for (int qc = 0; qc < 2; qc++) {
                int qh = qh0 - qc;
                int k2h = qh - 2 * ph + 1;
                if (qh < 0 || qh >= HQ || k2h < 0 || k2h > 3) continue;
#pragma unroll
                for (int dqw = 0; dqw < 2; dqw++) {
                    int qw = qw0 - dqw;
                    int k2w = qw - 2 * pw + 1;
                    if (qw < 0 || qw >= HQ || k2w < 0 || k2w > 3) continue;
                    e += sv[qc][p][k2w * 4 + (iw + 1 - 2 * qw)];
                }
            }
            if (e < best) { best = e; bestp = p; }
        }
        // reduce across the 8-lane group (lexicographic (e, p) = first occurrence)
#pragma unroll
        for (int off = 4; off > 0; off >>= 1) {
            float eo = __shfl_down_sync(0xffffffffu, best, off, 8);
            int po = __shfl_down_sync(0xffffffffu, bestp, off, 8);
            if (eo < best || (eo == best && po < bestp)) { best = eo; bestp = po; }
        }
        if (g == 0) sel_s[iw] = bestp;
    }
    __syncthreads();
    // scatter: 4 iw's at a time; group g4 = t>>6 handles iw = iter*4+g4, o = t&63
    int g4 = t >> 6, o = t & 63;
    for (int iter = 0; iter < 8; iter++) {
        int iw = iter * 4 + g4;
        int p = sel_s[iw];
        int ph = p >> 3, pw = p & 7;
        int qw0 = (iw + 1) >> 1;
        // stage am: 128 entries by 64 threads (coalesced over m)
#pragma unroll
        for (int rep = 0; rep < 2; rep++) {
            int e2 = rep * 64 + o;
            int qc = e2 >> 5, m = e2 & 31;
            int qh = qh0 - (qc >> 1), qw = qw0 - (qc & 1);
            float vv = 0.f;
            if (qh >= 0 && qh < HQ && qw >= 0 && qw < HQ) {
                int k2h = qh - 2 * ph + 1, k2w = qw - 2 * pw + 1;
                if (k2h >= 0 && k2h <= 3 && k2w >= 0 && k2w <= 3) {
                    if (g_y1[b][qh][qw][m] > 0.f) {
                        int k1 = (ih + 1 - 2 * qh) * 4 + (iw + 1 - 2 * qw);
                        vv = g_xw1[b][qh][qw][k1][m];
                    }
                }
            }
            am_s[g4][qc][m] = vv;
        }
        __syncthreads();
        float yy = g_y[b][p][o];
        if (yy > 0.f) {
            float acc = 0.f;
#pragma unroll
            for (int qc = 0; qc < 4; qc++) {
                int qh = qh0 - (qc >> 1), qw = qw0 - (qc & 1);
                if (qh < 0 || qh >= HQ || qw < 0 || qw >= HQ) continue;
                int k2h = qh - 2 * ph + 1, k2w = qw - 2 * pw + 1;
                if (k2h < 0 || k2h > 3 || k2w < 0 || k2w > 3) continue;
                int k2 = k2h * 4 + k2w;
#pragma unroll 8
                for (int m = 0; m < CM; m++)
                    acc += g_w2t[k2][m][o] * am_s[g4][qc][m];
            }
            if (acc != 0.f) atomicAdd(&g_ymask[b][p][o], acc);
        }
        __syncthreads();
    }
}

// ---------------------------------------------------------------------------
// Kernel H: final hopfield on y_masked -> output (B, CO, HP, HP)
// grid = BB*NP = 128 blocks, 256 threads
__global__ void kH(const float* __restrict__ Vm, float* __restrict__ out) {
    int blk = blockIdx.x;
    int b = blk / NP, p = blk % NP;
    __shared__ float yv[CO];
    __shared__ float wexp[NE];
    __shared__ float red[256];
    __shared__ float red2[4][CO];
    int t = threadIdx.x;
    if (t < CO) yv[t] = g_ymask[b][p][t];
    __syncthreads();
    float l[2];
    float lmax = -1e30f;
#pragma unroll
    for (int j = 0; j < 2; j++) {
        int k = t + 256 * j;
        float acc = 0.f;
#pragma unroll 8
        for (int o = 0; o < CO; o++) acc += g_KmT[o][k] * yv[o];
        l[j] = 0.125f * acc;
        lmax = fmaxf(lmax, l[j]);
    }
    red[t] = lmax;
    __syncthreads();
    for (int s = 128; s > 0; s >>= 1) {
        if (t < s) red[t] = fmaxf(red[t], red[t + s]);
        __syncthreads();
    }
    lmax = red[0];
    __syncthreads();
    float ssum = 0.f;
#pragma unroll
    for (int j = 0; j < 2; j++) {
        float e = expf(l[j] - lmax);
        wexp[t + 256 * j] = e;
        ssum += e;
    }
    red[t] = ssum;
    __syncthreads();
    for (int s = 128; s > 0; s >>= 1) {
        if (t < s) red[t] += red[t + s];
        __syncthreads();
    }
    float inv = 1.f / red[0];
    __syncthreads();
    {
        int o = t & 63, q4 = t >> 6;
        float acc = 0.f;
        int k0 = q4 * 128;
#pragma unroll 8
        for (int kk = 0; kk < 128; kk++) acc += wexp[k0 + kk] * Vm[(k0 + kk) * CO + o];
        red2[q4][o] = acc;
    }
    __syncthreads();
    if (t < CO) {
        float acc = (red2[0][t] + red2[1][t] + red2[2][t] + red2[3][t]) * inv;
        out[(b * CO + t) * NP + p] = acc;
    }
}

// ---------------------------------------------------------------------------
extern "C" void kernel_launch(void* const* d_in, const int* in_sizes, int n_in,
                              void* d_out, int out_size) {
    const float* x  = (const float*)d_in[0];  // (2,3,32,32)
    const float* w1 = (const float*)d_in[1];  // (32,3,4,4)
    const float* b1 = (const float*)d_in[2];  // (32,)
    const float* w2 = (const float*)d_in[3];  // (64,32,4,4)
    const float* b2 = (const float*)d_in[4];  // (64,)
    const float* Km = (const float*)d_in[5];  // (512,64)
    const float* Vm = (const float*)d_in[6];  // (512,64)
    float* out = (float*)d_out;               // (2,64,8,8)

    kA<<<BB * HQ * HQ, 32>>>(x, w1, b1, w2, Km);
    kBC<<<BB * NP, 256>>>(b2, Vm);
    kDE<<<BB * NP, 512>>>(w1, w2);
    kFG<<<BB * HH, 256>>>();
    kH<<<BB * NP, 256>>>(Vm, out);
}

// round 4
// speedup vs baseline: 3.2615x; 1.8305x over previous
#include <cuda_runtime.h>
#include <math_constants.h>

// Problem constants
#define BB 2
#define CIN 3
#define HH 32
#define WW 32
#define CM 32      // mid channels
#define HQ 16      // mid spatial
#define CO 64      // out channels
#define HP 8       // out spatial
#define NP 64      // HP*HP
#define NI 1024    // HH*WW
#define NE 512     // num embeddings

// Scratch in device globals (no allocations allowed)
__device__ float g_xw1[BB][HQ][HQ][16][CM];  // per-tap conv1 partials, [k1][m] (m contiguous)
__device__ float g_y1[BB][HQ][HQ][CM];       // relu(conv1), m contiguous
__device__ float g_y[BB][NP][CO];            // relu(conv2), o contiguous
__device__ float g_rm[BB][NP][CO];           // 2*(y - q(y)) * mask2
__device__ float g_v[BB][NP][16][16];        // [k2][k1]
__device__ float g_ymask[BB][NP][CO];
__device__ float g_w2t[16][CM][CO];          // w2 transposed: [k2][m][o], o contiguous
__device__ float g_KmT[CO][NE];              // K transposed: [o][k], k contiguous
__device__ int   g_sel[BB][NI];

// ---------------------------------------------------------------------------
// Kernel A: conv1 per-tap partials + relu(conv1); zero g_ymask; build w2t, KmT
// grid = BB*HQ*HQ = 512 blocks, 32 threads (one per mid channel m)
__global__ void kA(const float* __restrict__ x, const float* __restrict__ w1,
                   const float* __restrict__ b1, const float* __restrict__ w2,
                   const float* __restrict__ Km) {
    int blk = blockIdx.x;
    int b = blk / (HQ * HQ);
    int q = blk % (HQ * HQ);
    int qh = q / HQ, qw = q % HQ;
    __shared__ float sx[CIN][4][4];
    int t = threadIdx.x;
    int gid = blk * 32 + t;  // 0..16383
    if (gid < BB * NP * CO) (&g_ymask[0][0][0])[gid] = 0.f;
#pragma unroll
    for (int r = 0; r < 2; r++) {
        int idx = gid + r * 16384;  // 0..32767
        {
            int k2 = idx >> 11, m = (idx >> 6) & 31, o = idx & 63;
            g_w2t[k2][m][o] = w2[(o * CM + m) * 16 + k2];
        }
        {
            int o2 = idx >> 9, k = idx & 511;
            g_KmT[o2][k] = Km[k * CO + o2];
        }
    }
    for (int idx = t; idx < CIN * 16; idx += 32) {
        int c = idx / 16, k = idx % 16;
        int kh = k / 4, kw = k % 4;
        int xh = 2 * qh - 1 + kh, xw = 2 * qw - 1 + kw;
        float vv = 0.f;
        if (xh >= 0 && xh < HH && xw >= 0 && xw < WW)
            vv = x[((b * CIN + c) * HH + xh) * WW + xw];
        sx[c][kh][kw] = vv;
    }
    __syncthreads();
    int m = t;
    float acc = b1[m];
#pragma unroll
    for (int k = 0; k < 16; k++) {
        int kh = k / 4, kw = k % 4;
        float vv = 0.f;
#pragma unroll
        for (int c = 0; c < CIN; c++)
            vv += w1[(m * CIN + c) * 16 + k] * sx[c][kh][kw];
        g_xw1[b][qh][qw][k][m] = vv;
        acc += vv;
    }
    g_y1[b][qh][qw][m] = fmaxf(acc, 0.f);
}

// ---------------------------------------------------------------------------
// Shuffle-based block reductions over 256 threads (2-3 barriers)
__device__ __forceinline__ float blockMax256(float v, float* red8, int t) {
#pragma unroll
    for (int off = 16; off > 0; off >>= 1)
        v = fmaxf(v, __shfl_xor_sync(0xffffffffu, v, off));
    if ((t & 31) == 0) red8[t >> 5] = v;
    __syncthreads();
    if (t < 32) {
        float w = (t < 8) ? red8[t] : -CUDART_INF_F;
#pragma unroll
        for (int off = 4; off > 0; off >>= 1)
            w = fmaxf(w, __shfl_xor_sync(0xffffffffu, w, off));
        if (t == 0) red8[0] = w;
    }
    __syncthreads();
    return red8[0];
}
__device__ __forceinline__ float blockSum256(float v, float* red8, int t) {
#pragma unroll
    for (int off = 16; off > 0; off >>= 1)
        v += __shfl_xor_sync(0xffffffffu, v, off);
    if ((t & 31) == 0) red8[t >> 5] = v;
    __syncthreads();
    if (t < 32) {
        float w = (t < 8) ? red8[t] : 0.f;
#pragma unroll
        for (int off = 4; off > 0; off >>= 1)
            w += __shfl_xor_sync(0xffffffffu, w, off);
        if (t == 0) red8[0] = w;
    }
    __syncthreads();
    return red8[0];
}

// ---------------------------------------------------------------------------
// Kernel BC: conv2 + relu + hopfield -> rm residual, fused per (b,p)
// grid = BB*NP = 128 blocks, 256 threads
__global__ void kBC(const float* __restrict__ b2, const float* __restrict__ Vm) {
    int blk = blockIdx.x;
    int b = blk / NP, p = blk % NP;
    int ph = p / HP, pw = p % HP;
    __shared__ float sy1[16][CM];   // [k][m]
    __shared__ float yv[CO];
    __shared__ float wexp[NE];
    __shared__ float redA[8];
    __shared__ float redB[8];
    __shared__ float red2[4][CO];
    int t = threadIdx.x;
    for (int idx = t; idx < CM * 16; idx += 256) {
        int k = idx >> 5, m = idx & 31;
        int kh = k / 4, kw = k % 4;
        int qh = 2 * ph - 1 + kh, qw = 2 * pw - 1 + kw;
        float vv = 0.f;
        if (qh >= 0 && qh < HQ && qw >= 0 && qw < HQ) vv = g_y1[b][qh][qw][m];
        sy1[k][m] = vv;
    }
    __syncthreads();
    // conv2 via w2t[k][m][o] (coalesced over o): split m over 4 groups of 8
    {
        int o = t & 63, q4 = t >> 6;
        float acc = 0.f;
#pragma unroll
        for (int mm = 0; mm < 8; mm++) {
            int m = q4 * 8 + mm;
#pragma unroll
            for (int k = 0; k < 16; k++)
                acc += g_w2t[k][m][o] * sy1[k][m];
        }
        red2[q4][o] = acc;
    }
    __syncthreads();
    if (t < CO) {
        float acc = b2[t] + red2[0][t] + red2[1][t] + red2[2][t] + red2[3][t];
        float yy = fmaxf(acc, 0.f);
        yv[t] = yy;
        g_y[b][p][t] = yy;
    }
    __syncthreads();
    // logits via KmT[o][k] (coalesced over k)
    float l[2];
    float lmax = -1e30f;
#pragma unroll
    for (int j = 0; j < 2; j++) {
        int k = t + 256 * j;
        float acc = 0.f;
#pragma unroll 8
        for (int o = 0; o < CO; o++) acc += g_KmT[o][k] * yv[o];
        l[j] = 0.125f * acc;
        lmax = fmaxf(lmax, l[j]);
    }
    lmax = blockMax256(lmax, redA, t);
    float ssum = 0.f;
#pragma unroll
    for (int j = 0; j < 2; j++) {
        float e = expf(l[j] - lmax);
        wexp[t + 256 * j] = e;
        ssum += e;
    }
    float tot = blockSum256(ssum, redB, t);
    float inv = 1.f / tot;
    __syncthreads();
    // V accumulation: split k over 4 groups of 128
    {
        int o = t & 63, q4 = t >> 6;
        float acc = 0.f;
        int k0 = q4 * 128;
#pragma unroll 8
        for (int kk = 0; kk < 128; kk++) acc += wexp[k0 + kk] * Vm[(k0 + kk) * CO + o];
        red2[q4][o] = acc;
    }
    __syncthreads();
    if (t < CO) {
        float e = (red2[0][t] + red2[1][t] + red2[2][t] + red2[3][t]) * inv;
        float yy = yv[t];
        g_rm[b][p][t] = (yy > 0.f) ? 2.f * (yy - e) : 0.f;
    }
}

// ---------------------------------------------------------------------------
// Kernel DE: s (smem only, w2 via coalesced smem tiles) then v, fused per (b,p)
// grid = BB*NP = 128 blocks, 512 threads
__global__ void kDE(const float* __restrict__ w1, const float* __restrict__ w2) {
    int blk = blockIdx.x;
    int b = blk / NP, p = blk % NP;
    int ph = p / HP, pw = p % HP;
    __shared__ float r[CO];
    __shared__ float w1s[CM][16];
    __shared__ float sm[CM][16];
    __shared__ float sw[16][512];
    int t = threadIdx.x;
    if (t < CO) r[t] = g_rm[b][p][t];
    {
        int m = t / 16, k = t % 16;
        float acc = 0.f;
#pragma unroll
        for (int c = 0; c < CIN; c++) acc += w1[(m * CIN + c) * 16 + k];
        w1s[m][k] = acc;
    }
    __syncthreads();
    float acc = 0.f;
    for (int c = 0; c < 4; c++) {
#pragma unroll
        for (int j = 0; j < 16; j++) sw[j][t] = w2[(c * 16 + j) * 512 + t];
        __syncthreads();
#pragma unroll
        for (int j = 0; j < 16; j++) acc += r[c * 16 + j] * sw[j][t];
        __syncthreads();
    }
    {
        int m = t / 16, k2 = t % 16;
        int kh = k2 / 4, kw = k2 % 4;
        int qh = 2 * ph - 1 + kh, qw = 2 * pw - 1 + kw;
        float sv = 0.f;
        if (qh >= 0 && qh < HQ && qw >= 0 && qw < HQ && g_y1[b][qh][qw][m] > 0.f)
            sv = acc;
        sm[m][k2] = sv;
    }
    __syncthreads();
    if (t < 256) {
        int k2 = t / 16, k1 = t % 16;
        float a2 = 0.f;
#pragma unroll 8
        for (int m = 0; m < CM; m++) a2 += sm[m][k2] * w1s[m][k1];
        g_v[b][p][k2][k1] = a2;
    }
}

// ---------------------------------------------------------------------------
// Kernel F: one block per (b, ih) row: argmin over p for 32 iw -> g_sel
// grid = BB*HH = 64 blocks, 256 threads
__global__ void kF() {
    int blk = blockIdx.x;
    int b = blk / HH, ih = blk % HH;
    int qh0 = (ih + 1) >> 1;
    __shared__ float sv[2][64][16];
    int t = threadIdx.x;
    for (int idx = t; idx < 2 * 64 * 4; idx += 256) {
        int qc = idx >> 8;
        int rem = idx & 255;
        int p = rem >> 2, k2w = rem & 3;
        int qh = qh0 - qc;
        int ph = p >> 3;
        int k2h = qh - 2 * ph + 1;
        int k1h = ih + 1 - 2 * qh;
        float4 val = make_float4(0.f, 0.f, 0.f, 0.f);
        if (qh >= 0 && qh < HQ && k2h >= 0 && k2h <= 3)
            val = *(const float4*)&g_v[b][p][k2h * 4 + k2w][k1h * 4];
        *(float4*)&sv[qc][p][k2w * 4] = val;
    }
    __syncthreads();
    int iw = t >> 3, g = t & 7;
    int qw0 = (iw + 1) >> 1;
    float best = CUDART_INF_F;
    int bestp = 127;
    for (int pp = 0; pp < 8; pp++) {
        int p = g * 8 + pp;
        int ph = p >> 3, pw = p & 7;
        float e = 0.f;
#pragma unroll
        for (int qc = 0; qc < 2; qc++) {
            int qh = qh0 - qc;
            int k2h = qh - 2 * ph + 1;
            if (qh < 0 || qh >= HQ || k2h < 0 || k2h > 3) continue;
#pragma unroll
            for (int dqw = 0; dqw < 2; dqw++) {
                int qw = qw0 - dqw;
                int k2w = qw - 2 * pw + 1;
                if (qw < 0 || qw >= HQ || k2w < 0 || k2w > 3) continue;
                e += sv[qc][p][k2w * 4 + (iw + 1 - 2 * qw)];
            }
        }
        if (e < best) { best = e; bestp = p; }
    }
#pragma unroll
    for (int off = 4; off > 0; off >>= 1) {
        float eo = __shfl_down_sync(0xffffffffu, best, off, 8);
        int po = __shfl_down_sync(0xffffffffu, bestp, off, 8);
        if (eo < best || (eo == best && po < bestp)) { best = eo; bestp = po; }
    }
    if (g == 0) g_sel[b][ih * WW + iw] = bestp;
}

// ---------------------------------------------------------------------------
// Kernel G: scatter contrib into ymask; 4 pixels per block, no serial loop
// grid = BB*NI/4 = 512 blocks, 256 threads
__global__ void kG() {
    int t = threadIdx.x;
    int g4 = t >> 6, o = t & 63;
    int pix = blockIdx.x * 4 + g4;   // 0..2047
    int b = pix >> 10;
    int i = pix & 1023;
    int ih = i >> 5, iw = i & 31;
    int qh0 = (ih + 1) >> 1, qw0 = (iw + 1) >> 1;
    __shared__ float am_s[4][4][32];
    __shared__ int selp[4];
    if (o == 0) selp[g4] = g_sel[b][i];
    __syncthreads();
    int p = selp[g4];
    int ph = p >> 3, pw = p & 7;
    // stage am: 128 entries per pixel by its 64 threads (coalesced over m)
#pragma unroll
    for (int rep = 0; rep < 2; rep++) {
        int e2 = rep * 64 + o;
        int qc = e2 >> 5, m = e2 & 31;
        int qh = qh0 - (qc >> 1), qw = qw0 - (qc & 1);
        float vv = 0.f;
        if (qh >= 0 && qh < HQ && qw >= 0 && qw < HQ) {
            int k2h = qh - 2 * ph + 1, k2w = qw - 2 * pw + 1;
            if (k2h >= 0 && k2h <= 3 && k2w >= 0 && k2w <= 3) {
                if (g_y1[b][qh][qw][m] > 0.f) {
                    int k1 = (ih + 1 - 2 * qh) * 4 + (iw + 1 - 2 * qw);
                    vv = g_xw1[b][qh][qw][k1][m];
                }
            }
        }
        am_s[g4][qc][m] = vv;
    }
    __syncthreads();
    float yy = g_y[b][p][o];
    if (yy > 0.f) {
        float acc = 0.f;
#pragma unroll
        for (int qc = 0; qc < 4; qc++) {
            int qh = qh0 - (qc >> 1), qw = qw0 - (qc & 1);
            if (qh < 0 || qh >= HQ || qw < 0 || qw >= HQ) continue;
            int k2h = qh - 2 * ph + 1, k2w = qw - 2 * pw + 1;
            if (k2h < 0 || k2h > 3 || k2w < 0 || k2w > 3) continue;
            int k2 = k2h * 4 + k2w;
#pragma unroll 8
            for (int m = 0; m < CM; m++)
                acc += g_w2t[k2][m][o] * am_s[g4][qc][m];
        }
        if (acc != 0.f) atomicAdd(&g_ymask[b][p][o], acc);
    }
}

// ---------------------------------------------------------------------------
// Kernel H: final hopfield on y_masked -> output (B, CO, HP, HP)
// grid = BB*NP = 128 blocks, 256 threads
__global__ void kH(const float* __restrict__ Vm, float* __restrict__ out) {
    int blk = blockIdx.x;
    int b = blk / NP, p = blk % NP;
    __shared__ float yv[CO];
    __shared__ float wexp[NE];
    __shared__ float redA[8];
    __shared__ float redB[8];
    __shared__ float red2[4][CO];
    int t = threadIdx.x;
    if (t < CO) yv[t] = g_ymask[b][p][t];
    __syncthreads();
    float l[2];
    float lmax = -1e30f;
#pragma unroll
    for (int j = 0; j < 2; j++) {
        int k = t + 256 * j;
        float acc = 0.f;
#pragma unroll 8
        for (int o = 0; o < CO; o++) acc += g_KmT[o][k] * yv[o];
        l[j] = 0.125f * acc;
        lmax = fmaxf(lmax, l[j]);
    }
    lmax = blockMax256(lmax, redA, t);
    float ssum = 0.f;
#pragma unroll
    for (int j = 0; j < 2; j++) {
        float e = expf(l[j] - lmax);
        wexp[t + 256 * j] = e;
        ssum += e;
    }
    float tot = blockSum256(ssum, redB, t);
    float inv = 1.f / tot;
    __syncthreads();
    {
        int o = t & 63, q4 = t >> 6;
        float acc = 0.f;
        int k0 = q4 * 128;
#pragma unroll 8
        for (int kk = 0; kk < 128; kk++) acc += wexp[k0 + kk] * Vm[(k0 + kk) * CO + o];
        red2[q4][o] = acc;
    }
    __syncthreads();
    if (t < CO) {
        float acc = (red2[0][t] + red2[1][t] + red2[2][t] + red2[3][t]) * inv;
        out[(b * CO + t) * NP + p] = acc;
    }
}

// ---------------------------------------------------------------------------
extern "C" void kernel_launch(void* const* d_in, const int* in_sizes, int n_in,
                              void* d_out, int out_size) {
    const float* x  = (const float*)d_in[0];  // (2,3,32,32)
    const float* w1 = (const float*)d_in[1];  // (32,3,4,4)
    const float* b1 = (const float*)d_in[2];  // (32,)
    const float* w2 = (const float*)d_in[3];  // (64,32,4,4)
    const float* b2 = (const float*)d_in[4];  // (64,)
    const float* Km = (const float*)d_in[5];  // (512,64)
    const float* Vm = (const float*)d_in[6];  // (512,64)
    float* out = (float*)d_out;               // (2,64,8,8)

    kA<<<BB * HQ * HQ, 32>>>(x, w1, b1, w2, Km);
    kBC<<<BB * NP, 256>>>(b2, Vm);
    kDE<<<BB * NP, 512>>>(w1, w2);
    kF<<<BB * HH, 256>>>();
    kG<<<BB * NI / 4, 256>>>();
    kH<<<BB * NP, 256>>>(Vm, out);
}